// round 17
// baseline (speedup 1.0000x reference)
#include <cuda_runtime.h>
#include <cuda_fp16.h>
#include <cuda_bf16.h>

#define NN 51200
#define EE 1638400
#define GG 512
#define HCc 128
#define SLOPE 0.2f
#define GEMM_BLOCKS (NN / 64)   // 800

// ---------------- scratch (device globals; no allocation allowed) ----------------
__device__ __align__(16) __half2 g_xlh[NN * 64];   // xl fp16, 64 half2/row
__device__ __align__(16) __half2 g_xrh[NN * 64];   // xr fp16, 64 half2/row
__device__ float   g_h [NN * HCc];
__device__ int     g_deg[NN];            // zero-initialized; scan re-zeros after use
__device__ int     g_rowptr[NN + 1];
__device__ int     g_cursor[NN];
__device__ int     g_csr_src[EE];        // stores src*16 (premultiplied uint4-row offset)

// ---------------- f32x2 packed helpers (sm_103a FFMA2 etc.) ----------------
__device__ __forceinline__ void ffma2(unsigned long long& d,
                                      unsigned long long a, unsigned long long b) {
    asm("fma.rn.f32x2 %0, %1, %2, %3;" : "=l"(d) : "l"(a), "l"(b), "l"(d));
}
__device__ __forceinline__ unsigned long long ffma2r(unsigned long long a,
                                      unsigned long long b, unsigned long long c) {
    unsigned long long r;
    asm("fma.rn.f32x2 %0, %1, %2, %3;" : "=l"(r) : "l"(a), "l"(b), "l"(c));
    return r;
}
__device__ __forceinline__ unsigned long long pack2(float v) {
    unsigned long long r;
    unsigned u = __float_as_uint(v);
    asm("mov.b64 %0, {%1, %1};" : "=l"(r) : "r"(u));
    return r;
}
__device__ __forceinline__ unsigned long long f2pack(float lo, float hi) {
    unsigned long long r;
    asm("mov.b64 %0, {%1, %2};" : "=l"(r) : "f"(lo), "f"(hi));
    return r;
}
__device__ __forceinline__ float lo2(unsigned long long v) { return __uint_as_float((unsigned)v); }
__device__ __forceinline__ float hi2(unsigned long long v) { return __uint_as_float((unsigned)(v >> 32)); }

__device__ __forceinline__ unsigned h2_bits(__half2 h) {
    __half2_raw r = *(__half2_raw*)&h;
    return ((unsigned)r.y << 16) | (unsigned)r.x;
}

// ---------------- dual GEMM body (FFMA2): xl,xr (both fp16) ----------------
// ivp packed per-kk (4 u64 live at a time instead of 16) -> ~82 regs -> 3 blocks/SM.
template <int DIN>
__device__ __forceinline__ void gemm_body(int bid,
                                 const float* __restrict__ in,
                                 const float* __restrict__ Wl, const float* __restrict__ bl,
                                 const float* __restrict__ Wr, const float* __restrict__ br) {
    constexpr int KT = (DIN < 32) ? DIN : 32;
    __shared__ __align__(16) float sW[KT * 264];   // [k][o], stride 264
    __shared__ __align__(16) float sIn[64 * 36];   // [node][k], stride 36

    const int tid  = threadIdx.x;
    const int part = tid & 15;
    const int ng   = tid >> 4;

    unsigned long long acc[4][4][2];   // [node][quad][pair]
#pragma unroll
    for (int j = 0; j < 4; j++)
#pragma unroll
        for (int c = 0; c < 4; c++) { acc[j][c][0] = 0ull; acc[j][c][1] = 0ull; }

    for (int kt = 0; kt < DIN; kt += KT) {
        // stage W in float4 (coalesced)
        for (int idx = tid; idx < KT * 64; idx += 256) {
            int k  = idx >> 6;
            int oq = idx & 63;            // float4 index within 256 outputs
            float4 v = (oq < 32) ? ((const float4*)Wl)[(kt + k) * 32 + oq]
                                 : ((const float4*)Wr)[(kt + k) * 32 + (oq - 32)];
            *(float4*)&sW[k * 264 + oq * 4] = v;
        }
        // stage input tile in float4
        constexpr int KQ = KT / 4;
        for (int idx = tid; idx < 64 * KQ; idx += 256) {
            int n = idx / KQ;
            int q = idx - n * KQ;
            float4 v = ((const float4*)in)[((bid * 64 + n) * DIN + kt) / 4 + q];
            *(float4*)&sIn[n * 36 + q * 4] = v;
        }
        __syncthreads();

#pragma unroll
        for (int k = 0; k < KT; k += 4) {
            float4 iv[4];
#pragma unroll
            for (int j = 0; j < 4; j++)
                iv[j] = *(const float4*)&sIn[(ng * 4 + j) * 36 + k];
#pragma unroll
            for (int kk = 0; kk < 4; kk++) {
                unsigned long long ivp[4];
#pragma unroll
                for (int j = 0; j < 4; j++) {
                    const float* f = (const float*)&iv[j];
                    ivp[j] = pack2(f[kk]);
                }
#pragma unroll
                for (int c = 0; c < 4; c++) {
                    double2 wv = *(const double2*)&sW[(k + kk) * 264 + part * 4 + c * 64];
                    unsigned long long w01 = __double_as_longlong(wv.x);
                    unsigned long long w23 = __double_as_longlong(wv.y);
#pragma unroll
                    for (int j = 0; j < 4; j++) {
                        ffma2(acc[j][c][0], ivp[j], w01);
                        ffma2(acc[j][c][1], ivp[j], w23);
                    }
                }
            }
        }
        __syncthreads();
    }

    const int gn0 = bid * 64 + ng * 4;
#pragma unroll
    for (int j = 0; j < 4; j++) {
        const int node = gn0 + j;
#pragma unroll
        for (int c = 0; c < 4; c++) {
            const int o = part * 4 + c * 64;
            float4 v;
            v.x = lo2(acc[j][c][0]); v.y = hi2(acc[j][c][0]);
            v.z = lo2(acc[j][c][1]); v.w = hi2(acc[j][c][1]);
            if (c < 2) {
                v.x += bl[o]; v.y += bl[o + 1]; v.z += bl[o + 2]; v.w += bl[o + 3];
                __half2 h01 = __floats2half2_rn(v.x, v.y);
                __half2 h23 = __floats2half2_rn(v.z, v.w);
                unsigned long long pk = ((unsigned long long)h2_bits(h23) << 32)
                                        | (unsigned long long)h2_bits(h01);
                *(unsigned long long*)&g_xlh[node * 64 + o / 2] = pk;
            } else {
                const int o2 = o - 128;
                v.x += br[o2]; v.y += br[o2 + 1]; v.z += br[o2 + 2]; v.w += br[o2 + 3];
                __half2 h01 = __floats2half2_rn(v.x, v.y);
                __half2 h23 = __floats2half2_rn(v.z, v.w);
                unsigned long long pk = ((unsigned long long)h2_bits(h23) << 32)
                                        | (unsigned long long)h2_bits(h01);
                *(unsigned long long*)&g_xrh[node * 64 + o2 / 2] = pk;
            }
        }
    }
}

// ---------------- fused: layer-1 GEMM (blocks 0..799) + degree histogram ----------------
__global__ __launch_bounds__(256, 3) void fused_hist_gemm16(
                                 const int* __restrict__ dst, const float* __restrict__ x,
                                 const float* __restrict__ Wl, const float* __restrict__ bl,
                                 const float* __restrict__ Wr, const float* __restrict__ br) {
    if (blockIdx.x < GEMM_BLOCKS) {
        gemm_body<16>(blockIdx.x, x, Wl, bl, Wr, br);
    } else {
        const int4* d4 = (const int4*)dst;
        const int nthr = 1600 * 256;
        for (int e = (blockIdx.x - GEMM_BLOCKS) * 256 + threadIdx.x; e < EE / 4; e += nthr) {
            int4 v = d4[e];
            atomicAdd(&g_deg[v.x], 1);
            atomicAdd(&g_deg[v.y], 1);
            atomicAdd(&g_deg[v.z], 1);
            atomicAdd(&g_deg[v.w], 1);
        }
    }
}

__global__ __launch_bounds__(256, 3) void dual_gemm128_kernel(
                                 const float* __restrict__ Wl, const float* __restrict__ bl,
                                 const float* __restrict__ Wr, const float* __restrict__ br) {
    gemm_body<128>(blockIdx.x, g_h, Wl, bl, Wr, br);
}

// ---------------- CSR scan: coalesced tiled block-scan (1 block, 1024 thr) ----------------
__global__ void scan_kernel() {
    __shared__ int wsum[32];
    __shared__ int carry_s;
    const int t = threadIdx.x;
    const int lane = t & 31;
    const int wid = t >> 5;
    if (t == 0) carry_s = 0;
    __syncthreads();
    for (int tile = 0; tile < NN; tile += 1024) {
        int v = g_deg[tile + t];        // coalesced
        g_deg[tile + t] = 0;            // coalesced reset for next replay
        int x = v;
#pragma unroll
        for (int off = 1; off < 32; off <<= 1) {
            int y = __shfl_up_sync(0xffffffffu, x, off);
            if (lane >= off) x += y;
        }
        if (lane == 31) wsum[wid] = x;
        __syncthreads();
        if (wid == 0) {
            int s = wsum[lane];
#pragma unroll
            for (int off = 1; off < 32; off <<= 1) {
                int y = __shfl_up_sync(0xffffffffu, s, off);
                if (lane >= off) s += y;
            }
            wsum[lane] = s;
        }
        __syncthreads();
        const int base = carry_s;
        const int woff = wid ? wsum[wid - 1] : 0;
        const int excl = base + woff + x - v;
        g_rowptr[tile + t] = excl;      // coalesced
        g_cursor[tile + t] = excl;      // coalesced
        __syncthreads();
        if (t == 0) carry_s = base + wsum[31];
        __syncthreads();
    }
    if (t == 0) g_rowptr[NN] = carry_s;
}

// stores src*16 (uint4-row offset) so agg needs only an IADD per address
__global__ void scatter_kernel(const int* __restrict__ src, const int* __restrict__ dst) {
    const int4* s4 = (const int4*)src;
    const int4* d4 = (const int4*)dst;
    for (int e = blockIdx.x * blockDim.x + threadIdx.x; e < EE / 4; e += gridDim.x * blockDim.x) {
        int4 sv = s4[e];
        int4 dv = d4[e];
        g_csr_src[atomicAdd(&g_cursor[dv.x], 1)] = sv.x * 16;
        g_csr_src[atomicAdd(&g_cursor[dv.y], 1)] = sv.y * 16;
        g_csr_src[atomicAdd(&g_cursor[dv.z], 1)] = sv.z * 16;
        g_csr_src[atomicAdd(&g_cursor[dv.w], 1)] = sv.w * 16;
    }
}

// ---------------- fused GATv2 aggregation: 2 edge-slots x 16 lanes per warp ----------------
// fp16 t = a+xr; f32x2 dot in two chains: sA = Sum(t*att), sB = Sum(|t|*att);
// p = 0.6*sA + 0.4*sB. Accumulate Sum(w*t) f32x2; epilogue Sum(w*a) = Sum(w*t) - d*xr.
__global__ __launch_bounds__(128, 8) void gat_agg_kernel(const float* __restrict__ att,
                                                         const float* __restrict__ bias) {
    const int warp = threadIdx.x >> 5;
    const int lane = threadIdx.x & 31;
    const int slot = lane >> 4;       // 0..1
    const int sub  = lane & 15;       // 0..15, channels [sub*8, sub*8+8)
    const int node = blockIdx.x * 4 + warp;

    // xr (fp16) for this lane's 8 channels
    __half2 xr_h[4];
    *(uint4*)&xr_h[0] = ((const uint4*)g_xrh)[node * 16 + sub];

    // att in packed f32x2 registers (8 channels)
    unsigned long long attp[4];
    {
        const float4* ap = (const float4*)att + sub * 2;
        float4 A0 = ap[0], A1 = ap[1];
        attp[0] = f2pack(A0.x, A0.y); attp[1] = f2pack(A0.z, A0.w);
        attp[2] = f2pack(A1.x, A1.y); attp[3] = f2pack(A1.z, A1.w);
    }

    const int beg = g_rowptr[node];
    const int end = g_rowptr[node + 1];
    const int iters = (end - beg + 1) >> 1;

    unsigned long long acc[4] = {0ull, 0ull, 0ull, 0ull};
    float d = 0.f;

    if (iters > 0) {
        const int safe = end - 1;
        const uint4* base = (const uint4*)g_xlh;
        int k = beg + slot;
        int off0 = g_csr_src[min(k, safe)];
        int off1 = g_csr_src[min(k + 2, safe)];   // next-iteration offset (prefetched)
        uint4 ra = base[off0 + sub];
        for (int it = 0; it < iters; it++) {
            const uint4 na = base[off1 + sub];
            const int off2 = g_csr_src[min(k + 4, safe)];
            const bool valid = (k < end);

            __half2 a4[4];
            *(uint4*)&a4[0] = ra;

            unsigned long long tp[4];
            unsigned long long sA = 0ull, sB = 0ull;
#pragma unroll
            for (int i = 0; i < 4; i++) {
                __half2 th = __hadd2(a4[i], xr_h[i]);          // t = a+xr (fp16)
                float2 tf = __half22float2(th);
                tp[i] = f2pack(tf.x, tf.y);                    // t in f32x2
                unsigned long long ab = tp[i] & 0x7FFFFFFF7FFFFFFFull; // |t|
                sA = ffma2r(tp[i], attp[i], sA);               // Sum t*att
                sB = ffma2r(ab,    attp[i], sB);               // Sum |t|*att
            }
            float p = fmaf(0.6f, lo2(sA) + hi2(sA), 0.4f * (lo2(sB) + hi2(sB)));
            p += __shfl_xor_sync(0xffffffffu, p, 1);   // head spans 4 lanes
            p += __shfl_xor_sync(0xffffffffu, p, 2);

            float w = valid ? __expf(p) : 0.f;
            d += w;
            unsigned long long wp = pack2(w);
#pragma unroll
            for (int i = 0; i < 4; i++) ffma2(acc[i], tp[i], wp);   // Sum(w*t)

            ra = na; off1 = off2; k += 2;
        }
    }

    // merge the 2 slots (lanes differ in bit 4)
    float fx[4], fy[4];
#pragma unroll
    for (int i = 0; i < 4; i++) {
        float x = lo2(acc[i]), y = hi2(acc[i]);
        x += __shfl_xor_sync(0xffffffffu, x, 16);
        y += __shfl_xor_sync(0xffffffffu, y, 16);
        fx[i] = x; fy[i] = y;
    }
    d += __shfl_xor_sync(0xffffffffu, d, 16);

    if (slot == 0) {
        const float inv = 1.f / (d + 1e-16f);
        const bool has = end > beg;                 // deg-0: keep plain bias
        const float4* bp = (const float4*)bias + sub * 2;
        float* op = g_h + node * 128 + sub * 8;
#pragma unroll
        for (int q = 0; q < 2; q++) {
            float4 b = bp[q];
            if (has) {                              // Sum(w*a)/d = Sum(w*t)/d - xr
                float2 x0 = __half22float2(xr_h[2 * q]);
                float2 x1 = __half22float2(xr_h[2 * q + 1]);
                b.x -= x0.x; b.y -= x0.y; b.z -= x1.x; b.w -= x1.y;
            }
            float4 o;
            o.x = fmaxf(fmaf(fx[q * 2],     inv, b.x), 0.f);
            o.y = fmaxf(fmaf(fy[q * 2],     inv, b.y), 0.f);
            o.z = fmaxf(fmaf(fx[q * 2 + 1], inv, b.z), 0.f);
            o.w = fmaxf(fmaf(fy[q * 2 + 1], inv, b.w), 0.f);
            *(float4*)(op + q * 4) = o;
        }
    }
}

// ---------------- fused mean-pool + 3-layer MLP head (per-graph chain) ----------------
__global__ void pool_mlp_kernel(const int* __restrict__ batch,
                                const float* __restrict__ fc1_W, const float* __restrict__ fc1_b,
                                const float* __restrict__ bn1_g, const float* __restrict__ bn1_b,
                                const float* __restrict__ fc2_W, const float* __restrict__ fc2_b,
                                const float* __restrict__ bn2_g, const float* __restrict__ bn2_b,
                                const float* __restrict__ fc3_W, const float* __restrict__ fc3_b,
                                float* __restrict__ out) {
    const int g = blockIdx.x;
    const int t = threadIdx.x;  // 128 threads
    __shared__ int sb, se;
    __shared__ float s0buf[128];
    __shared__ float s1buf[128];
    __shared__ float w0[4], w1[4];
    if (t == 0) {
        int lo = 0, hi = NN;
        while (lo < hi) { int mid = (lo + hi) >> 1; if (batch[mid] < g) lo = mid + 1; else hi = mid; }
        sb = lo;
        hi = NN;
        while (lo < hi) { int mid = (lo + hi) >> 1; if (batch[mid] < g + 1) lo = mid + 1; else hi = mid; }
        se = lo;
    }
    __syncthreads();
    float s0 = 0.f, s1 = 0.f, s2 = 0.f, s3 = 0.f;
    int n = sb;
    for (; n + 4 <= se; n += 4) {
        s0 += g_h[(n + 0) * 128 + t];
        s1 += g_h[(n + 1) * 128 + t];
        s2 += g_h[(n + 2) * 128 + t];
        s3 += g_h[(n + 3) * 128 + t];
    }
    for (; n < se; n++) s0 += g_h[n * 128 + t];
    int cnt = se - sb;
    s0buf[t] = ((s0 + s1) + (s2 + s3)) / (float)(cnt > 0 ? cnt : 1);
    __syncthreads();

    const float bnscale = rsqrtf(1.0f + 1e-5f);
    {
        float a0 = fc1_b[t], a1 = 0.f;
#pragma unroll 4
        for (int k = 0; k < 128; k += 2) {
            a0 = fmaf(s0buf[k],     fc1_W[(k)     * 128 + t], a0);
            a1 = fmaf(s0buf[k + 1], fc1_W[(k + 1) * 128 + t], a1);
        }
        float a = a0 + a1;
        a = fmaxf(fmaf(a, bn1_g[t] * bnscale, bn1_b[t]), 0.f);
        s1buf[t] = a;
    }
    __syncthreads();
    {
        float a0 = fc2_b[t], a1 = 0.f;
#pragma unroll 4
        for (int k = 0; k < 128; k += 2) {
            a0 = fmaf(s1buf[k],     fc2_W[(k)     * 128 + t], a0);
            a1 = fmaf(s1buf[k + 1], fc2_W[(k + 1) * 128 + t], a1);
        }
        float a = a0 + a1;
        a = fmaxf(fmaf(a, bn2_g[t] * bnscale, bn2_b[t]), 0.f);
        s0buf[t] = a;
    }
    __syncthreads();
    {
        float p0 = s0buf[t] * fc3_W[t * 2 + 0];
        float p1 = s0buf[t] * fc3_W[t * 2 + 1];
#pragma unroll
        for (int off = 16; off; off >>= 1) {
            p0 += __shfl_xor_sync(0xffffffffu, p0, off);
            p1 += __shfl_xor_sync(0xffffffffu, p1, off);
        }
        if ((t & 31) == 0) { w0[t >> 5] = p0; w1[t >> 5] = p1; }
        __syncthreads();
        if (t == 0) out[g * 2 + 0] = w0[0] + w0[1] + w0[2] + w0[3] + fc3_b[0];
        if (t == 1) out[g * 2 + 1] = w1[0] + w1[1] + w1[2] + w1[3] + fc3_b[1];
    }
}

// ---------------- launch ----------------
extern "C" void kernel_launch(void* const* d_in, const int* in_sizes, int n_in,
                              void* d_out, int out_size) {
    const float* x      = (const float*)d_in[0];
    const int*   ei     = (const int*)  d_in[1];
    const int*   batch  = (const int*)  d_in[2];
    const float* l1_Wl  = (const float*)d_in[3];
    const float* l1_bl  = (const float*)d_in[4];
    const float* l1_Wr  = (const float*)d_in[5];
    const float* l1_br  = (const float*)d_in[6];
    const float* l1_att = (const float*)d_in[7];
    const float* l1_bias= (const float*)d_in[8];
    const float* l2_Wl  = (const float*)d_in[9];
    const float* l2_bl  = (const float*)d_in[10];
    const float* l2_Wr  = (const float*)d_in[11];
    const float* l2_br  = (const float*)d_in[12];
    const float* l2_att = (const float*)d_in[13];
    const float* l2_bias= (const float*)d_in[14];
    const float* fc1_W  = (const float*)d_in[15];
    const float* fc1_b  = (const float*)d_in[16];
    const float* bn1_g  = (const float*)d_in[17];
    const float* bn1_b  = (const float*)d_in[18];
    const float* fc2_W  = (const float*)d_in[19];
    const float* fc2_b  = (const float*)d_in[20];
    const float* bn2_g  = (const float*)d_in[21];
    const float* bn2_b  = (const float*)d_in[22];
    const float* fc3_W  = (const float*)d_in[23];
    const float* fc3_b  = (const float*)d_in[24];

    const int* src = ei;
    const int* dst = ei + EE;
    float* out = (float*)d_out;

    // 1: layer-1 GEMM fused with degree histogram
    fused_hist_gemm16<<<GEMM_BLOCKS + 1600, 256>>>(dst, x, l1_Wl, l1_bl, l1_Wr, l1_br);
    // 2: coalesced prefix scan (also re-zeros g_deg)
    scan_kernel<<<1, 1024>>>();
    // 3: CSR scatter
    scatter_kernel<<<1600, 256>>>(src, dst);
    // 4: layer-1 aggregation  <- ncu-profiled slot
    gat_agg_kernel<<<NN / 4, 128>>>(l1_att, l1_bias);
    // 5-6: layer 2
    dual_gemm128_kernel<<<GEMM_BLOCKS, 256>>>(l2_Wl, l2_bl, l2_Wr, l2_br);
    gat_agg_kernel<<<NN / 4, 128>>>(l2_att, l2_bias);
    // 7: fused pool + MLP head
    pool_mlp_kernel<<<GG, 128>>>(batch, fc1_W, fc1_b, bn1_g, bn1_b,
                                 fc2_W, fc2_b, bn2_g, bn2_b, fc3_W, fc3_b, out);
}